// round 16
// baseline (speedup 1.0000x reference)
#include <cuda_runtime.h>

#define EMB 64

typedef unsigned long long ull;

// ---- packed f32x2 helpers (Blackwell sm_103a) ----
__device__ __forceinline__ ull pk(float lo, float hi) {
    ull r;
    asm("mov.b64 %0, {%1, %2};" : "=l"(r) : "f"(lo), "f"(hi));
    return r;
}
__device__ __forceinline__ ull ffma2(ull a, ull b, ull c) {
    ull d;
    asm("fma.rn.f32x2 %0, %1, %2, %3;" : "=l"(d) : "l"(a), "l"(b), "l"(c));
    return d;
}
__device__ __forceinline__ float2 unpk(ull v) {
    float2 f;
    asm("mov.b64 {%0, %1}, %2;" : "=f"(f.x), "=f"(f.y) : "l"(v));
    return f;
}

// SINGLE fused kernel: one warp = one CTA = one segment.
//  Head (per warp, overlapped chip-wide):
//   a) wvo = w_value @ w_out computed cooperatively (lane -> rows lane, lane+32),
//      redistributed by shfl; c = b_value.w_out + b_out reduced by shfl.
//   b) segment bounds via 16-ary warp-parallel lower_bound: lanes 0-15 search n,
//      lanes 16-31 search n+1; 7 fixed rounds, ballot-driven.
//  Body: identical to the proven streaming loop — 8 lanes/row, 8 front-batched
//  evict-first LDG.128 per 16 rows, packed fma.rn.f32x2 dots, 3-level score
//  shfl, exp replicated x8, value partials reduced once per segment.
__global__ __launch_bounds__(32)
void fused_kernel(const float* __restrict__ emb,
                  const int*   __restrict__ ids,
                  const float* __restrict__ w_attn,
                  const float* __restrict__ w_value,
                  const float* __restrict__ b_value,
                  const float* __restrict__ w_out,
                  const float* __restrict__ b_out,
                  float* __restrict__ out,
                  int Btot, int Nimg) {
    const int n    = blockIdx.x;            // segment id
    const int lane = threadIdx.x;
    const int rs   = lane >> 3;             // row slot 0..3
    const int ci   = lane & 7;              // chunk index 0..7

    // ---------- head (a): fused output weights ----------
    float wvo_a = 0.f, wvo_b = 0.f;         // wvo[lane], wvo[lane+32]
    {
        const float4* wv4 = reinterpret_cast<const float4*>(w_value);
        const float4* wo4 = reinterpret_cast<const float4*>(w_out);
#pragma unroll
        for (int k = 0; k < 16; ++k) {
            const float4 wo = __ldg(wo4 + k);                  // broadcast
            const float4 ra = __ldg(wv4 + lane * 16 + k);
            const float4 rb = __ldg(wv4 + (lane + 32) * 16 + k);
            wvo_a = fmaf(ra.x, wo.x, fmaf(ra.y, wo.y, fmaf(ra.z, wo.z, fmaf(ra.w, wo.w, wvo_a))));
            wvo_b = fmaf(rb.x, wo.x, fmaf(rb.y, wo.y, fmaf(rb.z, wo.z, fmaf(rb.w, wo.w, wvo_b))));
        }
    }
    const float b0 = __ldg(b_out);
    float cb = __ldg(b_value + lane) * __ldg(w_out + lane)
             + __ldg(b_value + lane + 32) * __ldg(w_out + lane + 32);
#pragma unroll
    for (int o = 16; o; o >>= 1) cb += __shfl_xor_sync(0xffffffffu, cb, o);
    const float c = cb + b0;

    // redistribute wvo into this lane's two float4 chunks (ci, ci+8)
    float4 wv0, wv1;
    {
        const int s = 4 * ci;
        wv0.x = __shfl_sync(0xffffffffu, wvo_a, s + 0);
        wv0.y = __shfl_sync(0xffffffffu, wvo_a, s + 1);
        wv0.z = __shfl_sync(0xffffffffu, wvo_a, s + 2);
        wv0.w = __shfl_sync(0xffffffffu, wvo_a, s + 3);
        wv1.x = __shfl_sync(0xffffffffu, wvo_b, s + 0);
        wv1.y = __shfl_sync(0xffffffffu, wvo_b, s + 1);
        wv1.z = __shfl_sync(0xffffffffu, wvo_b, s + 2);
        wv1.w = __shfl_sync(0xffffffffu, wvo_b, s + 3);
    }

    const float4 wa0 = reinterpret_cast<const float4*>(w_attn)[ci];
    const float4 wa1 = reinterpret_cast<const float4*>(w_attn)[ci + 8];

    const ull waA = pk(wa0.x, wa0.y), waB = pk(wa0.z, wa0.w);
    const ull waC = pk(wa1.x, wa1.y), waD = pk(wa1.z, wa1.w);
    const ull wvA = pk(wv0.x, wv0.y), wvB = pk(wv0.z, wv0.w);
    const ull wvC = pk(wv1.x, wv1.y), wvD = pk(wv1.z, wv1.w);

    // ---------- head (b): segment bounds via 16-ary lower_bound ----------
    int lo = 0, hi = Btot;
    {
        const int target = n + (lane >> 4);    // group A: n, group B: n+1
        const int l = lane & 15;
#pragma unroll
        for (int round = 0; round < 7; ++round) {
            const int len = hi - lo;
            int idx = lo + ((len * l) >> 4);   // len*15 < 2^31 for Btot <= 128M
            if (idx >= Btot) idx = Btot - 1;
            const int v = __ldg(ids + idx);
            const unsigned bal = __ballot_sync(0xffffffffu, v < target);
            if (len > 0) {
                const unsigned gb = (lane < 16) ? (bal & 0xffffu) : (bal >> 16);
                if (gb == 0) {
                    hi = lo;                   // ids[lo] >= target -> answer = lo
                } else {
                    const int j   = 31 - __clz(gb);            // 0..15
                    const int pj  = lo + ((len * j) >> 4);
                    const int pj1 = (j < 15) ? lo + ((len * (j + 1)) >> 4) : hi;
                    lo = pj + 1;
                    hi = pj1;
                }
            }
        }
    }
    const int start = __shfl_sync(0xffffffffu, lo, 0);
    const int end   = __shfl_sync(0xffffffffu, lo, 16);
    const int cnt   = end - start;

    // ---------- body: streaming (identical to proven loop) ----------
    float se0 = 0.f, sev0 = 0.f, se1 = 0.f, sev1 = 0.f;
    float se2 = 0.f, sev2 = 0.f, se3 = 0.f, sev3 = 0.f;

    const float4* const pbase = reinterpret_cast<const float4*>(emb) + ci;
    const int mid = start + (cnt & ~15);    // 16 rows per iteration

    for (int base = start; base < mid; base += 16) {
        float4 e[8];
#pragma unroll
        for (int u = 0; u < 4; ++u) {
            const size_t ro = (size_t)(base + u * 4 + rs) << 4;
            e[2 * u]     = __ldcs(pbase + ro);
            e[2 * u + 1] = __ldcs(pbase + ro + 8);
        }
#pragma unroll
        for (int u = 0; u < 4; ++u) {
            const float4 a = e[2 * u], b = e[2 * u + 1];
            const ull pa = pk(a.x, a.y), pb = pk(a.z, a.w);
            const ull pc = pk(b.x, b.y), pd = pk(b.z, b.w);
            const ull s2 = ffma2(pa, waA, ffma2(pb, waB, ffma2(pc, waC, ffma2(pd, waD, 0ULL))));
            const ull v2 = ffma2(pa, wvA, ffma2(pb, wvB, ffma2(pc, wvC, ffma2(pd, wvD, 0ULL))));
            const float2 sf = unpk(s2);
            const float2 vf = unpk(v2);
            float sp = sf.x + sf.y;
            const float vp = vf.x + vf.y;
#pragma unroll
            for (int o = 4; o; o >>= 1) sp += __shfl_xor_sync(0xffffffffu, sp, o);
            const float ex = __expf(sp);            // replicated on the 8-lane group
            if      (u == 0) { se0 += ex; sev0 = fmaf(ex, vp, sev0); }
            else if (u == 1) { se1 += ex; sev1 = fmaf(ex, vp, sev1); }
            else if (u == 2) { se2 += ex; sev2 = fmaf(ex, vp, sev2); }
            else             { se3 += ex; sev3 = fmaf(ex, vp, sev3); }
        }
    }

    if (mid < end) {                        // masked tail (up to 15 rows)
#pragma unroll
        for (int u = 0; u < 4; ++u) {
            const int row = mid + u * 4 + rs;
            const bool v = row < end;
            float4 a = make_float4(0.f, 0.f, 0.f, 0.f);
            float4 b = make_float4(0.f, 0.f, 0.f, 0.f);
            if (v) {
                const size_t ro = (size_t)row << 4;
                a = __ldcs(pbase + ro);
                b = __ldcs(pbase + ro + 8);
            }
            const ull pa = pk(a.x, a.y), pb = pk(a.z, a.w);
            const ull pc = pk(b.x, b.y), pd = pk(b.z, b.w);
            const ull s2 = ffma2(pa, waA, ffma2(pb, waB, ffma2(pc, waC, ffma2(pd, waD, 0ULL))));
            const ull v2 = ffma2(pa, wvA, ffma2(pb, wvB, ffma2(pc, wvC, ffma2(pd, wvD, 0ULL))));
            const float2 sf = unpk(s2);
            const float2 vf = unpk(v2);
            float sp = sf.x + sf.y;
            const float vp = vf.x + vf.y;
#pragma unroll
            for (int o = 4; o; o >>= 1) sp += __shfl_xor_sync(0xffffffffu, sp, o);
            const float ex = v ? __expf(sp) : 0.f;
            se0 += ex; sev0 = fmaf(ex, vp, sev0);
        }
    }

    // ---------- once-per-segment reduction ----------
    float se  = (se0 + se1) + (se2 + se3);       // replicated within 8-lane groups
    float sev = (sev0 + sev1) + (sev2 + sev3);
    se += __shfl_xor_sync(0xffffffffu, se, 8);
    se += __shfl_xor_sync(0xffffffffu, se, 16);
#pragma unroll
    for (int o = 16; o; o >>= 1) sev += __shfl_xor_sync(0xffffffffu, sev, o);

    const float r = (cnt == 0) ? b0 : (sev / se + c);   // replicated

    if (lane == 0) {
        out[Btot + n]        = r;          // r_images
        out[Btot + Nimg + n] = (float)n;   // unique_ids
    }
    for (int i = start + lane; i < end; i += 32) out[i] = r;   // r_reflections
}

extern "C" void kernel_launch(void* const* d_in, const int* in_sizes, int n_in,
                              void* d_out, int out_size) {
    const float* emb     = (const float*)d_in[0];
    const int*   ids     = (const int*)  d_in[1];
    const float* w_attn  = (const float*)d_in[2];
    // d_in[3] = b_attn: cancels under softmax shift invariance
    const float* w_value = (const float*)d_in[4];
    const float* b_value = (const float*)d_in[5];
    const float* w_out   = (const float*)d_in[6];
    const float* b_out   = (const float*)d_in[7];
    float* out = (float*)d_out;

    const int Btot = in_sizes[0] / EMB;          // 1048576
    const int Nimg = (out_size - Btot) / 2;      // 4096

    fused_kernel<<<Nimg, 32>>>(emb, ids, w_attn, w_value, b_value, w_out, b_out,
                               out, Btot, Nimg);
}

// round 17
// speedup vs baseline: 1.2023x; 1.2023x over previous
#include <cuda_runtime.h>

#define EMB 64
#define NSEG_MAX 4097
#define THREADS 256

typedef unsigned long long ull;

__device__ float g_wvo[EMB];     // w_value @ w_out
__device__ float g_c;            // b_value.w_out + b_out
__device__ float g_b0;           // b_out[0]
__device__ int   g_starts[NSEG_MAX];

// ---- packed f32x2 helpers (Blackwell sm_103a) ----
__device__ __forceinline__ ull pk(float lo, float hi) {
    ull r;
    asm("mov.b64 %0, {%1, %2};" : "=l"(r) : "f"(lo), "f"(hi));
    return r;
}
__device__ __forceinline__ ull ffma2(ull a, ull b, ull c) {
    ull d;
    asm("fma.rn.f32x2 %0, %1, %2, %3;" : "=l"(d) : "l"(a), "l"(b), "l"(c));
    return d;
}
__device__ __forceinline__ float2 unpk(ull v) {
    float2 f;
    asm("mov.b64 {%0, %1}, %2;" : "=f"(f.x), "=f"(f.y) : "l"(v));
    return f;
}

// Kernel 1: segment-bounds scan (int4-vectorized, shfl for neighbor) +
// fused-head precompute in block 0 (overlapped with the 4MB ids stream).
__global__ __launch_bounds__(THREADS)
void bounds_kernel(const int*   __restrict__ ids,
                   const float* __restrict__ w_value,
                   const float* __restrict__ b_value,
                   const float* __restrict__ w_out,
                   const float* __restrict__ b_out,
                   int Btot, int Nimg) {
    const int tid = threadIdx.x;
    const int t   = blockIdx.x * THREADS + tid;   // vector index (4 ids each)
    const int i0  = t * 4;

    if (blockIdx.x == 0 && tid < EMB) {
        float s = 0.f;
#pragma unroll
        for (int h = 0; h < EMB; ++h)
            s = fmaf(__ldg(w_value + tid * EMB + h), __ldg(w_out + h), s);
        g_wvo[tid] = s;
        if (tid == 0) {
            float c = 0.f;
#pragma unroll
            for (int h = 0; h < EMB; ++h) c = fmaf(__ldg(b_value + h), __ldg(w_out + h), c);
            g_c  = c + __ldg(b_out);
            g_b0 = __ldg(b_out);
        }
    }

    if (i0 < Btot) {
        const int4 cur = __ldg(reinterpret_cast<const int4*>(ids) + t);
        int prev = __shfl_up_sync(0xffffffffu, cur.w, 1);
        if ((tid & 31) == 0 && i0 > 0) prev = __ldg(ids + i0 - 1);

        if (i0 == 0) {
            for (int j = 0; j <= cur.x; ++j) g_starts[j] = 0;
        } else {
            for (int j = prev + 1; j <= cur.x; ++j) g_starts[j] = i0;
        }
        for (int j = cur.x + 1; j <= cur.y; ++j) g_starts[j] = i0 + 1;
        for (int j = cur.y + 1; j <= cur.z; ++j) g_starts[j] = i0 + 2;
        for (int j = cur.z + 1; j <= cur.w; ++j) g_starts[j] = i0 + 3;

        if (i0 + 4 >= Btot) {
            for (int j = cur.w + 1; j <= Nimg; ++j) g_starts[j] = Btot;
        }
    }
}

// Kernel 2: one warp = one CTA = one segment (proven R15 body). Launched with
// PDL: prologue (w_attn load+pack) runs before cudaGridDependencySynchronize();
// everything dependent on bounds_kernel (g_starts/g_wvo/g_c) comes after.
__global__ __launch_bounds__(32)
void pool_kernel(const float* __restrict__ emb,
                 const float* __restrict__ w_attn,
                 float* __restrict__ out,
                 int Btot, int Nimg) {
    const int n    = blockIdx.x;            // segment id
    const int lane = threadIdx.x;
    const int rs   = lane >> 3;             // row slot 0..3
    const int ci   = lane & 7;              // chunk index 0..7

    // ---- independent prologue (overlaps with bounds_kernel under PDL) ----
    const float4 wa0 = reinterpret_cast<const float4*>(w_attn)[ci];
    const float4 wa1 = reinterpret_cast<const float4*>(w_attn)[ci + 8];
    const ull waA = pk(wa0.x, wa0.y), waB = pk(wa0.z, wa0.w);
    const ull waC = pk(wa1.x, wa1.y), waD = pk(wa1.z, wa1.w);

    // ---- wait for bounds_kernel's grid (g_starts, g_wvo, g_c, g_b0) ----
#if __CUDA_ARCH__ >= 900
    cudaGridDependencySynchronize();
#endif

    const float4 wv0 = reinterpret_cast<const float4*>(g_wvo)[ci];
    const float4 wv1 = reinterpret_cast<const float4*>(g_wvo)[ci + 8];
    const ull wvA = pk(wv0.x, wv0.y), wvB = pk(wv0.z, wv0.w);
    const ull wvC = pk(wv1.x, wv1.y), wvD = pk(wv1.z, wv1.w);

    const int start = g_starts[n];
    const int end   = g_starts[n + 1];
    const int cnt   = end - start;

    float se0 = 0.f, sev0 = 0.f, se1 = 0.f, sev1 = 0.f;
    float se2 = 0.f, sev2 = 0.f, se3 = 0.f, sev3 = 0.f;

    const float4* const pbase = reinterpret_cast<const float4*>(emb) + ci;
    const int mid = start + (cnt & ~15);    // 16 rows per iteration

    // ---- main loop: 8 independent LDG.128 (evict-first) front-batched ----
    for (int base = start; base < mid; base += 16) {
        float4 e[8];
#pragma unroll
        for (int u = 0; u < 4; ++u) {
            const size_t ro = (size_t)(base + u * 4 + rs) << 4;
            e[2 * u]     = __ldcs(pbase + ro);
            e[2 * u + 1] = __ldcs(pbase + ro + 8);
        }
#pragma unroll
        for (int u = 0; u < 4; ++u) {
            const float4 a = e[2 * u], b = e[2 * u + 1];
            const ull pa = pk(a.x, a.y), pb = pk(a.z, a.w);
            const ull pc = pk(b.x, b.y), pd = pk(b.z, b.w);
            const ull s2 = ffma2(pa, waA, ffma2(pb, waB, ffma2(pc, waC, ffma2(pd, waD, 0ULL))));
            const ull v2 = ffma2(pa, wvA, ffma2(pb, wvB, ffma2(pc, wvC, ffma2(pd, wvD, 0ULL))));
            const float2 sf = unpk(s2);
            const float2 vf = unpk(v2);
            float sp = sf.x + sf.y;
            const float vp = vf.x + vf.y;
#pragma unroll
            for (int o = 4; o; o >>= 1) sp += __shfl_xor_sync(0xffffffffu, sp, o);
            const float ex = __expf(sp);            // replicated on the 8-lane group
            if      (u == 0) { se0 += ex; sev0 = fmaf(ex, vp, sev0); }
            else if (u == 1) { se1 += ex; sev1 = fmaf(ex, vp, sev1); }
            else if (u == 2) { se2 += ex; sev2 = fmaf(ex, vp, sev2); }
            else             { se3 += ex; sev3 = fmaf(ex, vp, sev3); }
        }
    }

    // ---- masked tail (up to 15 rows) ----
    if (mid < end) {
#pragma unroll
        for (int u = 0; u < 4; ++u) {
            const int row = mid + u * 4 + rs;
            const bool v = row < end;
            float4 a = make_float4(0.f, 0.f, 0.f, 0.f);
            float4 b = make_float4(0.f, 0.f, 0.f, 0.f);
            if (v) {
                const size_t ro = (size_t)row << 4;
                a = __ldcs(pbase + ro);
                b = __ldcs(pbase + ro + 8);
            }
            const ull pa = pk(a.x, a.y), pb = pk(a.z, a.w);
            const ull pc = pk(b.x, b.y), pd = pk(b.z, b.w);
            const ull s2 = ffma2(pa, waA, ffma2(pb, waB, ffma2(pc, waC, ffma2(pd, waD, 0ULL))));
            const ull v2 = ffma2(pa, wvA, ffma2(pb, wvB, ffma2(pc, wvC, ffma2(pd, wvD, 0ULL))));
            const float2 sf = unpk(s2);
            const float2 vf = unpk(v2);
            float sp = sf.x + sf.y;
            const float vp = vf.x + vf.y;
#pragma unroll
            for (int o = 4; o; o >>= 1) sp += __shfl_xor_sync(0xffffffffu, sp, o);
            const float ex = v ? __expf(sp) : 0.f;
            se0 += ex; sev0 = fmaf(ex, vp, sev0);
        }
    }

    // ---- once-per-segment reduction (intra-warp only) ----
    float se  = (se0 + se1) + (se2 + se3);       // replicated within 8-lane groups
    float sev = (sev0 + sev1) + (sev2 + sev3);
    se += __shfl_xor_sync(0xffffffffu, se, 8);
    se += __shfl_xor_sync(0xffffffffu, se, 16);
#pragma unroll
    for (int o = 16; o; o >>= 1) sev += __shfl_xor_sync(0xffffffffu, sev, o);

    const float r = (cnt == 0) ? g_b0 : (sev / se + g_c);   // replicated

    if (lane == 0) {
        out[Btot + n]        = r;          // r_images
        out[Btot + Nimg + n] = (float)n;   // unique_ids
    }
    for (int i = start + lane; i < end; i += 32) out[i] = r;   // r_reflections
}

extern "C" void kernel_launch(void* const* d_in, const int* in_sizes, int n_in,
                              void* d_out, int out_size) {
    const float* emb     = (const float*)d_in[0];
    const int*   ids     = (const int*)  d_in[1];
    const float* w_attn  = (const float*)d_in[2];
    // d_in[3] = b_attn: cancels under softmax shift invariance
    const float* w_value = (const float*)d_in[4];
    const float* b_value = (const float*)d_in[5];
    const float* w_out   = (const float*)d_in[6];
    const float* b_out   = (const float*)d_in[7];
    float* out = (float*)d_out;

    const int Btot = in_sizes[0] / EMB;          // 1048576 (divisible by 4)
    const int Nimg = (out_size - Btot) / 2;      // 4096

    const int nvec = (Btot + 3) / 4;             // int4 elements
    bounds_kernel<<<(nvec + THREADS - 1) / THREADS, THREADS>>>(
        ids, w_value, b_value, w_out, b_out, Btot, Nimg);

    // Pool with PDL: may begin launching while bounds_kernel drains; the
    // in-kernel cudaGridDependencySynchronize() orders the dependent reads.
    cudaLaunchAttribute attrs[1];
    attrs[0].id = cudaLaunchAttributeProgrammaticStreamSerialization;
    attrs[0].val.programmaticStreamSerializationAllowed = 1;

    cudaLaunchConfig_t cfg = {};
    cfg.gridDim  = dim3(Nimg, 1, 1);
    cfg.blockDim = dim3(32, 1, 1);
    cfg.dynamicSmemBytes = 0;
    cfg.stream   = 0;                 // same (captured) stream as <<<>>> above
    cfg.attrs    = attrs;
    cfg.numAttrs = 1;

    cudaError_t err = cudaLaunchKernelEx(&cfg, pool_kernel, emb, w_attn, out, Btot, Nimg);
    if (err != cudaSuccess) {
        // Fallback: plain launch (still correct, just no overlap)
        pool_kernel<<<Nimg, 32>>>(emb, w_attn, out, Btot, Nimg);
    }
}